// round 2
// baseline (speedup 1.0000x reference)
#include <cuda_runtime.h>
#include <math.h>

#define TILE_W 64
#define TILE_H 32
#define HALO 5
#define R_ROWS (TILE_H + 2*HALO)   // 42
#define R_COLS (TILE_W + 2*HALO)   // 74
#define NTHREADS 256
#define IMG 512
#define PLANES 48                  // 16 batch * 3 channels

#define C1v 0.0001f                // 0.01^2
#define C2v 0.0009f                // 0.03^2

#define SMEM_IN_BYTES  (R_ROWS * R_COLS * (int)sizeof(float2))          // 24864
#define SMEM_H4_BYTES  (R_ROWS * TILE_W * (int)sizeof(float4))          // 43008
#define SMEM_H1_BYTES  (R_ROWS * TILE_W * (int)sizeof(float))           // 10752
#define SMEM_BYTES     (SMEM_IN_BYTES + SMEM_H4_BYTES + SMEM_H1_BYTES)  // 78624

struct Wei { float w[11]; };

__device__ double g_accum;

__global__ void init_kernel() { g_accum = 0.0; }

__global__ __launch_bounds__(NTHREADS, 2)
void ssim_kernel(const float* __restrict__ pred, const float* __restrict__ targ, Wei W) {
    extern __shared__ unsigned char smem_raw[];
    float2* s_in = (float2*)smem_raw;
    float4* s_h4 = (float4*)(smem_raw + SMEM_IN_BYTES);
    float*  s_h1 = (float*)(smem_raw + SMEM_IN_BYTES + SMEM_H4_BYTES);
    __shared__ float red[NTHREADS / 32];

    const int tid = threadIdx.x;
    const int x0 = blockIdx.x * TILE_W;
    const int y0 = blockIdx.y * TILE_H;
    const long long plane_off = (long long)blockIdx.z * (IMG * IMG);
    const float* p = pred + plane_off;
    const float* t = targ + plane_off;

    // ---- Phase 1: load halo tile, transform (x+1)/2; OOB = 0 (matches zero pad) ----
    for (int idx = tid; idx < R_ROWS * R_COLS; idx += NTHREADS) {
        int r = idx / R_COLS;
        int c = idx - r * R_COLS;
        int gy = y0 - HALO + r;
        int gx = x0 - HALO + c;
        float a = 0.0f, b = 0.0f;
        if ((unsigned)gy < IMG && (unsigned)gx < IMG) {
            int g = gy * IMG + gx;
            a = fmaf(0.5f, p[g], 0.5f);
            b = fmaf(0.5f, t[g], 0.5f);
        }
        s_in[idx] = make_float2(a, b);
    }
    __syncthreads();

    // ---- Phase 2: horizontal blur of 5 fields, 8-wide register sliding window ----
    // units: 42 rows x 8 column-groups = 336
    for (int u = tid; u < R_ROWS * (TILE_W / 8); u += NTHREADS) {
        int r  = u >> 3;
        int c0 = (u & 7) << 3;
        float amp[8], amt[8], app[8], att[8], apt[8];
        #pragma unroll
        for (int o = 0; o < 8; ++o) { amp[o]=0.f; amt[o]=0.f; app[o]=0.f; att[o]=0.f; apt[o]=0.f; }
        const float2* row = s_in + r * R_COLS + c0;
        #pragma unroll
        for (int k = 0; k < 18; ++k) {
            float2 v = row[k];
            float aa = v.x * v.x;
            float bb = v.y * v.y;
            float ab = v.x * v.y;
            #pragma unroll
            for (int o = 0; o < 8; ++o) {
                int tp = k - o;
                if (tp >= 0 && tp < 11) {
                    float wk = W.w[tp];
                    amp[o] = fmaf(wk, v.x, amp[o]);
                    amt[o] = fmaf(wk, v.y, amt[o]);
                    app[o] = fmaf(wk, aa,  app[o]);
                    att[o] = fmaf(wk, bb,  att[o]);
                    apt[o] = fmaf(wk, ab,  apt[o]);
                }
            }
        }
        #pragma unroll
        for (int o = 0; o < 8; ++o) {
            s_h4[r * TILE_W + c0 + o] = make_float4(amp[o], amt[o], app[o], att[o]);
            s_h1[r * TILE_W + c0 + o] = apt[o];
        }
    }
    __syncthreads();

    // ---- Phase 3: vertical blur (8-tall sliding window) + SSIM map ----
    const int c  = tid & (TILE_W - 1);
    const int r0 = (tid >> 6) << 3;   // 0,8,16,24
    float vmp[8], vmt[8], vpp[8], vtt[8], vpt[8];
    #pragma unroll
    for (int o = 0; o < 8; ++o) { vmp[o]=0.f; vmt[o]=0.f; vpp[o]=0.f; vtt[o]=0.f; vpt[o]=0.f; }
    #pragma unroll
    for (int k = 0; k < 18; ++k) {
        float4 h4 = s_h4[(r0 + k) * TILE_W + c];
        float  h1 = s_h1[(r0 + k) * TILE_W + c];
        #pragma unroll
        for (int o = 0; o < 8; ++o) {
            int tp = k - o;
            if (tp >= 0 && tp < 11) {
                float wk = W.w[tp];
                vmp[o] = fmaf(wk, h4.x, vmp[o]);
                vmt[o] = fmaf(wk, h4.y, vmt[o]);
                vpp[o] = fmaf(wk, h4.z, vpp[o]);
                vtt[o] = fmaf(wk, h4.w, vtt[o]);
                vpt[o] = fmaf(wk, h1,   vpt[o]);
            }
        }
    }

    float local = 0.0f;
    #pragma unroll
    for (int o = 0; o < 8; ++o) {
        float mu_p = vmp[o], mu_t = vmt[o];
        float mpp = mu_p * mu_p;
        float mtt = mu_t * mu_t;
        float mpt = mu_p * mu_t;
        float sp  = vpp[o] - mpp;
        float st_ = vtt[o] - mtt;
        float spt = vpt[o] - mpt;
        float num = (2.0f * mpt + C1v) * (2.0f * spt + C2v);
        float den = (mpp + mtt + C1v) * (sp + st_ + C2v);
        local += __fdividef(num, den);
    }

    // ---- Block reduction -> double atomic ----
    #pragma unroll
    for (int s = 16; s > 0; s >>= 1)
        local += __shfl_down_sync(0xffffffffu, local, s);
    if ((tid & 31) == 0) red[tid >> 5] = local;
    __syncthreads();
    if (tid < 8) {
        float v = red[tid];
        #pragma unroll
        for (int s = 4; s > 0; s >>= 1)
            v += __shfl_down_sync(0xffu, v, s);
        if (tid == 0) atomicAdd(&g_accum, (double)v);
    }
}

__global__ void fin_kernel(float* out) {
    const double N = (double)PLANES * (double)(IMG * IMG);
    out[0] = (float)(1.0 - g_accum / N);
}

extern "C" void kernel_launch(void* const* d_in, const int* in_sizes, int n_in,
                              void* d_out, int out_size) {
    const float* pred = (const float*)d_in[0];
    const float* targ = (const float*)d_in[1];

    // Gaussian window (sigma=1.5, size=11), computed in double, normalized.
    Wei W;
    {
        double g[11], s = 0.0;
        for (int i = 0; i < 11; ++i) {
            double d = (double)(i - 5);
            g[i] = exp(-(d * d) / 4.5);
            s += g[i];
        }
        for (int i = 0; i < 11; ++i) W.w[i] = (float)(g[i] / s);
    }

    cudaFuncSetAttribute(ssim_kernel, cudaFuncAttributeMaxDynamicSharedMemorySize, SMEM_BYTES);

    init_kernel<<<1, 1>>>();
    dim3 grid(IMG / TILE_W, IMG / TILE_H, PLANES);
    ssim_kernel<<<grid, NTHREADS, SMEM_BYTES>>>(pred, targ, W);
    fin_kernel<<<1, 1>>>((float*)d_out);
}

// round 4
// speedup vs baseline: 1.5203x; 1.5203x over previous
#include <cuda_runtime.h>

#define TILE_W 64
#define TILE_H 32
#define HALO 5
#define R_ROWS (TILE_H + 2*HALO)   // 42
#define R_COLS (TILE_W + 2*HALO)   // 74
#define PADC 75                    // odd word stride for input planes
#define PADH 65                    // odd word stride for h-blur planes
#define NTHREADS 384
#define IMG 512
#define PLANES 48
#define GRID_X (IMG / TILE_W)      // 8
#define GRID_Y (IMG / TILE_H)      // 16
#define NBLOCKS (GRID_X * GRID_Y * PLANES)  // 6144

#define C1v 0.0001f
#define C2v 0.0009f

// smem: s_p[42][75], s_t[42][75], 5 x h[42][65]  => 19950 floats = 79800 B
#define OFF_P  0
#define OFF_T  (R_ROWS * PADC)
#define OFF_H  (2 * R_ROWS * PADC)
#define HPLANE (R_ROWS * PADH)
#define SMEM_FLOATS (2 * R_ROWS * PADC + 5 * HPLANE)
#define SMEM_BYTES  (SMEM_FLOATS * 4)

// Gaussian(sigma=1.5, k=11), normalized; double-precision values as fp32
// literals so ptxas emits FFMA-imm (rt_SMSP=1, 2x fp32 FMA throughput).
__device__ constexpr float Wc[11] = {
    0.00102838f, 0.00759876f, 0.03600077f, 0.10936070f, 0.21300553f,
    0.26601172f, 0.21300553f, 0.10936070f, 0.03600077f, 0.00759876f,
    0.00102838f
};

__device__ double g_accum = 0.0;
__device__ unsigned int g_count = 0u;

__global__ __launch_bounds__(NTHREADS, 2)
void ssim_kernel(const float* __restrict__ pred, const float* __restrict__ targ,
                 float* __restrict__ out) {
    extern __shared__ float s[];
    __shared__ float red[NTHREADS / 32];

    const int tid = threadIdx.x;
    const int x0 = blockIdx.x * TILE_W;
    const int y0 = blockIdx.y * TILE_H;
    const long long plane_off = (long long)blockIdx.z * (IMG * IMG);
    const float* p = pred + plane_off;
    const float* t = targ + plane_off;

    // ---- Phase 1: load halo tile, transform (x+1)/2; OOB = 0 (zero pad) ----
    for (int idx = tid; idx < R_ROWS * R_COLS; idx += NTHREADS) {
        int r = idx / R_COLS;
        int c = idx - r * R_COLS;
        int gy = y0 - HALO + r;
        int gx = x0 - HALO + c;
        float a = 0.0f, b = 0.0f;
        if ((unsigned)gy < IMG && (unsigned)gx < IMG) {
            int g = gy * IMG + gx;
            a = fmaf(0.5f, p[g], 0.5f);
            b = fmaf(0.5f, t[g], 0.5f);
        }
        s[OFF_P + r * PADC + c] = a;
        s[OFF_T + r * PADC + c] = b;
    }
    __syncthreads();

    // ---- Phase 2: horizontal blur of 5 fields, 8-wide register window ----
    // 336 units (r in [0,42), col-group in [0,8)), exactly one per thread.
    if (tid < R_ROWS * (TILE_W / 8)) {
        int r  = tid % R_ROWS;          // r-fast: warp lanes span rows ->
        int cg = tid / R_ROWS;          // odd row stride = conflict-free LDS
        int c0 = cg << 3;
        float amp[8], amt[8], app[8], att[8], apt[8];
        #pragma unroll
        for (int o = 0; o < 8; ++o) { amp[o]=0.f; amt[o]=0.f; app[o]=0.f; att[o]=0.f; apt[o]=0.f; }
        const float* rp = s + OFF_P + r * PADC + c0;
        const float* rt = s + OFF_T + r * PADC + c0;
        #pragma unroll
        for (int k = 0; k < 18; ++k) {
            float a = rp[k];
            float b = rt[k];
            float aa = a * a;
            float bb = b * b;
            float ab = a * b;
            #pragma unroll
            for (int o = 0; o < 8; ++o) {
                int tp = k - o;                 // compile-time after unroll
                if (tp >= 0 && tp < 11) {
                    amp[o] = fmaf(Wc[tp], a,  amp[o]);
                    amt[o] = fmaf(Wc[tp], b,  amt[o]);
                    app[o] = fmaf(Wc[tp], aa, app[o]);
                    att[o] = fmaf(Wc[tp], bb, att[o]);
                    apt[o] = fmaf(Wc[tp], ab, apt[o]);
                }
            }
        }
        int ob = r * PADH + c0;
        #pragma unroll
        for (int o = 0; o < 8; ++o) {
            s[OFF_H + 0 * HPLANE + ob + o] = amp[o];
            s[OFF_H + 1 * HPLANE + ob + o] = amt[o];
            s[OFF_H + 2 * HPLANE + ob + o] = app[o];
            s[OFF_H + 3 * HPLANE + ob + o] = att[o];
            s[OFF_H + 4 * HPLANE + ob + o] = apt[o];
        }
    }
    __syncthreads();

    // ---- Phase 3: vertical blur (8-tall window) + SSIM map ----
    float local = 0.0f;
    if (tid < 256) {
        const int c  = tid & (TILE_W - 1);
        const int r0 = (tid >> 6) << 3;     // 0,8,16,24
        float vmp[8], vmt[8], vpp[8], vtt[8], vpt[8];
        #pragma unroll
        for (int o = 0; o < 8; ++o) { vmp[o]=0.f; vmt[o]=0.f; vpp[o]=0.f; vtt[o]=0.f; vpt[o]=0.f; }
        #pragma unroll
        for (int k = 0; k < 18; ++k) {
            int base = (r0 + k) * PADH + c;
            float hmp = s[OFF_H + 0 * HPLANE + base];
            float hmt = s[OFF_H + 1 * HPLANE + base];
            float hpp = s[OFF_H + 2 * HPLANE + base];
            float htt = s[OFF_H + 3 * HPLANE + base];
            float hpt = s[OFF_H + 4 * HPLANE + base];
            #pragma unroll
            for (int o = 0; o < 8; ++o) {
                int tp = k - o;
                if (tp >= 0 && tp < 11) {
                    vmp[o] = fmaf(Wc[tp], hmp, vmp[o]);
                    vmt[o] = fmaf(Wc[tp], hmt, vmt[o]);
                    vpp[o] = fmaf(Wc[tp], hpp, vpp[o]);
                    vtt[o] = fmaf(Wc[tp], htt, vtt[o]);
                    vpt[o] = fmaf(Wc[tp], hpt, vpt[o]);
                }
            }
        }
        #pragma unroll
        for (int o = 0; o < 8; ++o) {
            float mu_p = vmp[o], mu_t = vmt[o];
            float mpp = mu_p * mu_p;
            float mtt = mu_t * mu_t;
            float mpt = mu_p * mu_t;
            float sp  = vpp[o] - mpp;
            float st_ = vtt[o] - mtt;
            float spt = vpt[o] - mpt;
            float num = (2.0f * mpt + C1v) * (2.0f * spt + C2v);
            float den = (mpp + mtt + C1v) * (sp + st_ + C2v);
            local += __fdividef(num, den);
        }
    }

    // ---- Block reduction ----
    #pragma unroll
    for (int sh = 16; sh > 0; sh >>= 1)
        local += __shfl_down_sync(0xffffffffu, local, sh);
    if ((tid & 31) == 0) red[tid >> 5] = local;
    __syncthreads();
    if (tid < 32) {
        float v = (tid < (NTHREADS / 32)) ? red[tid] : 0.0f;
        #pragma unroll
        for (int sh = 8; sh > 0; sh >>= 1)
            v += __shfl_down_sync(0xffffffffu, v, sh);
        if (tid == 0) {
            atomicAdd(&g_accum, (double)v);
            __threadfence();
            unsigned prev = atomicAdd(&g_count, 1u);
            if (prev == (unsigned)(NBLOCKS - 1)) {
                // last block: finalize, then reset for the next (graph) replay
                double tot = atomicAdd(&g_accum, 0.0);
                const double N = (double)PLANES * (double)(IMG * IMG);
                out[0] = (float)(1.0 - tot / N);
                g_accum = 0.0;
                g_count = 0u;
            }
        }
    }
}

extern "C" void kernel_launch(void* const* d_in, const int* in_sizes, int n_in,
                              void* d_out, int out_size) {
    const float* pred = (const float*)d_in[0];
    const float* targ = (const float*)d_in[1];

    cudaFuncSetAttribute(ssim_kernel, cudaFuncAttributeMaxDynamicSharedMemorySize, SMEM_BYTES);

    dim3 grid(GRID_X, GRID_Y, PLANES);
    ssim_kernel<<<grid, NTHREADS, SMEM_BYTES>>>(pred, targ, (float*)d_out);
}

// round 5
// speedup vs baseline: 1.9593x; 1.2887x over previous
#include <cuda_runtime.h>

#define TILE_W 64
#define TILE_H 32
#define HALO 5
#define R_ROWS (TILE_H + 2*HALO)   // 42
#define R_COLS (TILE_W + 2*HALO)   // 74
#define NTHREADS 256
#define IMG 512
#define PLANES 48
#define GRID_X (IMG / TILE_W)      // 8
#define GRID_Y (IMG / TILE_H)      // 16
#define NBLOCKS (GRID_X * GRID_Y * PLANES)  // 6144

#define C1v 0.0001f
#define C2v 0.0009f

// Union row-block layout: per row r, 325 floats at r*325:
//   input:  p at [0..74], t at [75..149]         (live until h row r written)
//   hplane: q*65 + c, q=0..4, c=0..63            (overwrites input row r)
// 42 * 325 = 13650 floats = 54600 B  -> 4 CTAs/SM.
#define ROWSTRIDE 325
#define SMEM_BYTES (R_ROWS * ROWSTRIDE * 4)

// Gaussian(sigma=1.5, k=11) as literals -> ptxas emits FFMA-imm (rt_SMSP=1).
__device__ constexpr float Wc[11] = {
    0.00102838f, 0.00759876f, 0.03600077f, 0.10936070f, 0.21300553f,
    0.26601172f, 0.21300553f, 0.10936070f, 0.03600077f, 0.00759876f,
    0.00102838f
};

__device__ double g_accum = 0.0;
__device__ unsigned int g_count = 0u;

__device__ __forceinline__ void hblur_row(const float* __restrict__ s, int r, int c0,
                                          float* amp, float* amt, float* app,
                                          float* att, float* apt) {
    #pragma unroll
    for (int o = 0; o < 8; ++o) { amp[o]=0.f; amt[o]=0.f; app[o]=0.f; att[o]=0.f; apt[o]=0.f; }
    const float* rp = s + r * ROWSTRIDE + c0;
    const float* rt = rp + 75;
    #pragma unroll
    for (int k = 0; k < 18; ++k) {
        float a = rp[k];
        float b = rt[k];
        float aa = a * a;
        float bb = b * b;
        float ab = a * b;
        #pragma unroll
        for (int o = 0; o < 8; ++o) {
            int tp = k - o;                 // compile-time after unroll
            if (tp >= 0 && tp < 11) {
                amp[o] = fmaf(Wc[tp], a,  amp[o]);
                amt[o] = fmaf(Wc[tp], b,  amt[o]);
                app[o] = fmaf(Wc[tp], aa, app[o]);
                att[o] = fmaf(Wc[tp], bb, att[o]);
                apt[o] = fmaf(Wc[tp], ab, apt[o]);
            }
        }
    }
}

__device__ __forceinline__ void hblur_store(float* __restrict__ s, int r, int c0,
                                            const float* amp, const float* amt,
                                            const float* app, const float* att,
                                            const float* apt) {
    float* rb = s + r * ROWSTRIDE + c0;
    #pragma unroll
    for (int o = 0; o < 8; ++o) {
        rb[0 * 65 + o] = amp[o];
        rb[1 * 65 + o] = amt[o];
        rb[2 * 65 + o] = app[o];
        rb[3 * 65 + o] = att[o];
        rb[4 * 65 + o] = apt[o];
    }
}

__global__ __launch_bounds__(NTHREADS, 4)
void ssim_kernel(const float* __restrict__ pred, const float* __restrict__ targ,
                 float* __restrict__ out) {
    extern __shared__ float s[];
    __shared__ float red[NTHREADS / 32];

    const int tid = threadIdx.x;
    const int x0 = blockIdx.x * TILE_W;
    const int y0 = blockIdx.y * TILE_H;
    const long long plane_off = (long long)blockIdx.z * (IMG * IMG);
    const float* p = pred + plane_off;
    const float* t = targ + plane_off;

    // ---- Phase 1: load halo tile, (x+1)/2; OOB = 0 (zero pad) ----
    {
        int r = tid / R_COLS;            // 0..3 for tid<256
        int c = tid - r * R_COLS;
        for (int idx = tid; idx < R_ROWS * R_COLS; idx += NTHREADS) {
            int gy = y0 - HALO + r;
            int gx = x0 - HALO + c;
            float a = 0.0f, b = 0.0f;
            if ((unsigned)gy < IMG && (unsigned)gx < IMG) {
                int g = gy * IMG + gx;
                a = fmaf(0.5f, p[g], 0.5f);
                b = fmaf(0.5f, t[g], 0.5f);
            }
            float* rb = s + r * ROWSTRIDE;
            rb[c]      = a;
            rb[75 + c] = b;
            c += NTHREADS - 3 * R_COLS;  // +34
            r += 3;
            if (c >= R_COLS) { c -= R_COLS; ++r; }
        }
    }
    __syncthreads();

    // ---- Round 1 compute: h-blur rows 0..31 (256 units, one per thread) ----
    float amp[8], amt[8], app[8], att[8], apt[8];
    const int r1 = tid & 31;             // lanes span rows: stride 325 (odd) -> conflict-free
    const int c1 = (tid >> 5) << 3;
    hblur_row(s, r1, c1, amp, amt, app, att, apt);
    __syncthreads();

    // ---- Round 1 write-back (overwrites input rows 0..31)
    //      + Round 2 compute: rows 32..41 (80 units; reads rows untouched above) ----
    hblur_store(s, r1, c1, amp, amt, app, att, apt);
    const int r2 = 32 + (tid % 10);
    const int c2 = (tid / 10) << 3;
    if (tid < 80)
        hblur_row(s, r2, c2, amp, amt, app, att, apt);
    __syncthreads();

    if (tid < 80)
        hblur_store(s, r2, c2, amp, amt, app, att, apt);
    __syncthreads();

    // ---- Phase 3: vertical blur (8-tall window) + SSIM; all 256 threads ----
    const int c  = tid & (TILE_W - 1);
    const int r0 = (tid >> 6) << 3;      // 0,8,16,24
    float vmp[8], vmt[8], vpp[8], vtt[8], vpt[8];
    #pragma unroll
    for (int o = 0; o < 8; ++o) { vmp[o]=0.f; vmt[o]=0.f; vpp[o]=0.f; vtt[o]=0.f; vpt[o]=0.f; }
    #pragma unroll
    for (int k = 0; k < 18; ++k) {
        const float* rb = s + (r0 + k) * ROWSTRIDE + c;
        float hmp = rb[0 * 65];
        float hmt = rb[1 * 65];
        float hpp = rb[2 * 65];
        float htt = rb[3 * 65];
        float hpt = rb[4 * 65];
        #pragma unroll
        for (int o = 0; o < 8; ++o) {
            int tp = k - o;
            if (tp >= 0 && tp < 11) {
                vmp[o] = fmaf(Wc[tp], hmp, vmp[o]);
                vmt[o] = fmaf(Wc[tp], hmt, vmt[o]);
                vpp[o] = fmaf(Wc[tp], hpp, vpp[o]);
                vtt[o] = fmaf(Wc[tp], htt, vtt[o]);
                vpt[o] = fmaf(Wc[tp], hpt, vpt[o]);
            }
        }
    }

    float local = 0.0f;
    #pragma unroll
    for (int o = 0; o < 8; ++o) {
        float mu_p = vmp[o], mu_t = vmt[o];
        float mpp = mu_p * mu_p;
        float mtt = mu_t * mu_t;
        float mpt = mu_p * mu_t;
        float sp  = vpp[o] - mpp;
        float st_ = vtt[o] - mtt;
        float spt = vpt[o] - mpt;
        float num = (2.0f * mpt + C1v) * (2.0f * spt + C2v);
        float den = (mpp + mtt + C1v) * (sp + st_ + C2v);
        local += __fdividef(num, den);
    }

    // ---- Block reduction -> device accumulator; last block finalizes ----
    #pragma unroll
    for (int sh = 16; sh > 0; sh >>= 1)
        local += __shfl_down_sync(0xffffffffu, local, sh);
    if ((tid & 31) == 0) red[tid >> 5] = local;
    __syncthreads();
    if (tid < 32) {
        float v = (tid < (NTHREADS / 32)) ? red[tid] : 0.0f;
        #pragma unroll
        for (int sh = 4; sh > 0; sh >>= 1)
            v += __shfl_down_sync(0xffffffffu, v, sh);
        if (tid == 0) {
            atomicAdd(&g_accum, (double)v);
            __threadfence();
            unsigned prev = atomicAdd(&g_count, 1u);
            if (prev == (unsigned)(NBLOCKS - 1)) {
                double tot = atomicAdd(&g_accum, 0.0);
                const double N = (double)PLANES * (double)(IMG * IMG);
                out[0] = (float)(1.0 - tot / N);
                g_accum = 0.0;
                g_count = 0u;
            }
        }
    }
}

extern "C" void kernel_launch(void* const* d_in, const int* in_sizes, int n_in,
                              void* d_out, int out_size) {
    const float* pred = (const float*)d_in[0];
    const float* targ = (const float*)d_in[1];

    cudaFuncSetAttribute(ssim_kernel, cudaFuncAttributeMaxDynamicSharedMemorySize, SMEM_BYTES);

    dim3 grid(GRID_X, GRID_Y, PLANES);
    ssim_kernel<<<grid, NTHREADS, SMEM_BYTES>>>(pred, targ, (float*)d_out);
}